// round 15
// baseline (speedup 1.0000x reference)
#include <cuda_runtime.h>
#include <cuda_fp16.h>

#define Bd 8
#define Td 512
#define Cd 512
#define NHd 8
#define HDd 64
#define Md (Bd * Td)            // 4096
#define QKVN (3 * Cd)           // 1536

__device__ float g_qkv[Md * QKVN];
__device__ float g_y[Md * Cd];
__device__ float2 g_qstat[Md];
__device__ float2 g_kstat[Md];

// pack two floats into half2 bits (lo, hi)
__device__ __forceinline__ unsigned f2h2(float lo, float hi) {
    unsigned u;
    asm("cvt.rn.f16x2.f32 %0, %1, %2;" : "=r"(u) : "f"(hi), "f"(lo));
    return u;
}
__device__ __forceinline__ uint2 pack4(float4 v) {
    return make_uint2(f2h2(v.x, v.y), f2h2(v.z, v.w));
}
__device__ __forceinline__ void mma_f16(float c[4],
    unsigned a0, unsigned a1, unsigned a2, unsigned a3,
    unsigned b0, unsigned b1)
{
    asm volatile(
        "mma.sync.aligned.m16n8k16.row.col.f32.f16.f16.f32 "
        "{%0,%1,%2,%3}, {%4,%5,%6,%7}, {%8,%9}, {%0,%1,%2,%3};"
        : "+f"(c[0]), "+f"(c[1]), "+f"(c[2]), "+f"(c[3])
        : "r"(a0), "r"(a1), "r"(a2), "r"(a3), "r"(b0), "r"(b1));
}

__device__ __forceinline__ unsigned smaddr(const void* p) {
    return (unsigned)__cvta_generic_to_shared(p);
}
__device__ __forceinline__ void ldsm_x4(unsigned& r0, unsigned& r1,
                                        unsigned& r2, unsigned& r3, unsigned addr) {
    asm volatile("ldmatrix.sync.aligned.m8n8.x4.shared.b16 {%0,%1,%2,%3}, [%4];"
        : "=r"(r0), "=r"(r1), "=r"(r2), "=r"(r3) : "r"(addr));
}
// A-fragment m16xk16 at rows rb..rb+15, halfs ko..ko+15
__device__ __forceinline__ void ldA(unsigned a[4], const __half* base, int pitch,
                                    int rb, int ko, int lane) {
    int row = rb + (lane & 15);
    int kk = ko + ((lane >> 4) << 3);
    unsigned addr = smaddr(base + row * pitch + kk);
    ldsm_x4(a[0], a[1], a[2], a[3], addr);
}
// B-fragments for TWO n8 subtiles (rows nb..nb+15), halfs ko..ko+15
__device__ __forceinline__ void ldB2(unsigned b[4], const __half* base, int pitch,
                                     int nb, int ko, int lane) {
    int row = nb + (lane & 7) + ((lane >> 4) << 3);
    int kk = ko + (((lane >> 3) & 1) << 3);
    unsigned addr = smaddr(base + row * pitch + kk);
    ldsm_x4(b[0], b[1], b[2], b[3], addr);
}

// ---------------------------------------------------------------------------
// fp16 SGEMM, scalar-LDS operands (R12 layout), double-buffered smem:
// one __syncthreads per k-block. BM x 64 tile, BK=32, 256 threads.
// ---------------------------------------------------------------------------
#define GP2 20
template<int BM>
__global__ __launch_bounds__(256) void sgemm_bias_kernel(
    const float* __restrict__ A, const float* __restrict__ W,
    const float* __restrict__ bias, float* __restrict__ out,
    int Kdim, int Ndim)
{
    constexpr int MI = BM / 64;
    constexpr int AL = BM / 32;
    __shared__ unsigned As[2][BM * GP2];
    __shared__ unsigned Bs[2][64 * GP2];
    const int tid = threadIdx.x;
    const int lane = tid & 31, warp = tid >> 5;
    const int g = lane >> 2, tig = lane & 3;
    const int wm = (warp & 3) * (BM / 4);
    const int wn = (warp >> 2) << 5;
    const int m0 = blockIdx.y * BM, n0 = blockIdx.x << 6;

    const int lrow = tid >> 3;             // 0..31
    const int lk4 = (tid & 7) << 2;        // halfs 0,4..28
    const int lk2 = lk4 >> 1;              // half2 idx

    float c[MI][4][4] = {};
    float4 avr[AL], bvr[2];

    const int niter = Kdim >> 5;

    // prologue: block 0 -> stage 0 ; block 1 -> regs
    #pragma unroll
    for (int i = 0; i < AL; i++)
        avr[i] = *(const float4*)&A[(size_t)(m0 + lrow + (i << 5)) * Kdim + lk4];
    #pragma unroll
    for (int i = 0; i < 2; i++)
        bvr[i] = *(const float4*)&W[(size_t)(n0 + lrow + (i << 5)) * Kdim + lk4];
    #pragma unroll
    for (int i = 0; i < AL; i++)
        *(uint2*)&As[0][(lrow + (i << 5)) * GP2 + lk2] = pack4(avr[i]);
    #pragma unroll
    for (int i = 0; i < 2; i++)
        *(uint2*)&Bs[0][(lrow + (i << 5)) * GP2 + lk2] = pack4(bvr[i]);
    if (niter > 1) {
        #pragma unroll
        for (int i = 0; i < AL; i++)
            avr[i] = *(const float4*)&A[(size_t)(m0 + lrow + (i << 5)) * Kdim + 32 + lk4];
        #pragma unroll
        for (int i = 0; i < 2; i++)
            bvr[i] = *(const float4*)&W[(size_t)(n0 + lrow + (i << 5)) * Kdim + 32 + lk4];
    }
    __syncthreads();

    for (int it = 0; it < niter; it++) {
        const int p = it & 1;
        if (it + 1 < niter) {
            #pragma unroll
            for (int i = 0; i < AL; i++)
                *(uint2*)&As[p ^ 1][(lrow + (i << 5)) * GP2 + lk2] = pack4(avr[i]);
            #pragma unroll
            for (int i = 0; i < 2; i++)
                *(uint2*)&Bs[p ^ 1][(lrow + (i << 5)) * GP2 + lk2] = pack4(bvr[i]);
        }
        if (it + 2 < niter) {
            const int kn = (it + 2) << 5;
            #pragma unroll
            for (int i = 0; i < AL; i++)
                avr[i] = *(const float4*)&A[(size_t)(m0 + lrow + (i << 5)) * Kdim + kn + lk4];
            #pragma unroll
            for (int i = 0; i < 2; i++)
                bvr[i] = *(const float4*)&W[(size_t)(n0 + lrow + (i << 5)) * Kdim + kn + lk4];
        }

        #pragma unroll
        for (int ks = 0; ks < 2; ks++) {
            const int ko = ks << 3;                // half2 offset
            unsigned a[MI][4];
            #pragma unroll
            for (int i = 0; i < MI; i++) {
                int mb = wm + (i << 4);
                a[i][0] = As[p][(mb + g) * GP2 + ko + tig];
                a[i][1] = As[p][(mb + g + 8) * GP2 + ko + tig];
                a[i][2] = As[p][(mb + g) * GP2 + ko + 4 + tig];
                a[i][3] = As[p][(mb + g + 8) * GP2 + ko + 4 + tig];
            }
            #pragma unroll
            for (int j = 0; j < 4; j++) {
                int nb = wn + (j << 3) + g;
                unsigned b0 = Bs[p][nb * GP2 + ko + tig];
                unsigned b1 = Bs[p][nb * GP2 + ko + 4 + tig];
                #pragma unroll
                for (int i = 0; i < MI; i++)
                    mma_f16(c[i][j], a[i][0], a[i][1], a[i][2], a[i][3], b0, b1);
            }
        }
        __syncthreads();
    }

    #pragma unroll
    for (int i = 0; i < MI; i++) {
        #pragma unroll
        for (int j = 0; j < 4; j++) {
            int row = m0 + wm + (i << 4) + g;
            int col = n0 + wn + (j << 3) + (tig << 1);
            float b0 = bias[col], b1 = bias[col + 1];
            *(float2*)&out[(size_t)row * Ndim + col] =
                make_float2(c[i][j][0] + b0, c[i][j][1] + b1);
            *(float2*)&out[(size_t)(row + 8) * Ndim + col] =
                make_float2(c[i][j][2] + b0, c[i][j][3] + b1);
        }
    }
}

// ---------------------------------------------------------------------------
// Per-row LN stats (mu, rstd) for q and k segments. One warp per row-segment.
// ---------------------------------------------------------------------------
__global__ __launch_bounds__(256) void ln_stats_kernel(
    const float* __restrict__ qkv,
    float2* __restrict__ qstat, float2* __restrict__ kstat)
{
    const int gw = (blockIdx.x * 256 + threadIdx.x) >> 5;   // 0..8191
    const int lane = threadIdx.x & 31;
    const int row = gw >> 1, seg = gw & 1;
    const float* p = qkv + (size_t)row * QKVN + seg * Cd;
    float s = 0.f, ss = 0.f;
    #pragma unroll
    for (int i = 0; i < 4; i++) {
        float4 v = *(const float4*)&p[(lane << 2) + (i << 7)];
        s  += v.x + v.y + v.z + v.w;
        ss += v.x * v.x + v.y * v.y + v.z * v.z + v.w * v.w;
    }
    #pragma unroll
    for (int o = 16; o; o >>= 1) {
        s  += __shfl_xor_sync(0xffffffffu, s, o);
        ss += __shfl_xor_sync(0xffffffffu, ss, o);
    }
    if (lane == 0) {
        float mu = s * (1.0f / 512.0f);
        float var = ss * (1.0f / 512.0f) - mu * mu;
        float2 st = make_float2(mu, rsqrtf(var + 1e-5f));
        if (seg) kstat[row] = st; else qstat[row] = st;
    }
}

// ---------------------------------------------------------------------------
// Flash attention (R13 LDSM core) with LN applied during smem fill.
// ---------------------------------------------------------------------------
#define TP2 36
#define TPH 72
#define PCP 132
#define ATTN_SMEM ((2304 * 4 + 4608 + 8448 + 256) * 4)

__global__ __launch_bounds__(256, 2) void attn_kernel(
    const float* __restrict__ qkv,
    const float* __restrict__ rel_emb,
    const float2* __restrict__ qstat, const float2* __restrict__ kstat,
    const float* __restrict__ qgam, const float* __restrict__ qbet,
    const float* __restrict__ kgam, const float* __restrict__ kbet,
    float* __restrict__ yout)
{
    const int blk = blockIdx.x;
    const int qb = 7 - (blk & 7);        // heavy blocks first
    const int h  = (blk >> 3) & 7;
    const int b  = blk >> 6;
    const int q0 = qb << 6;
    const int ntiles = qb + 1;

    extern __shared__ unsigned smu[];
    unsigned* QF = smu;                  // Q [row][k] half2
    unsigned* RF = smu + 2304;           // rel tiles x2; V reuses slot0
    unsigned* KF = smu + 6912;           // K [key][d] half2
    unsigned* PF = smu + 9216;           // probabilities [row][key] half2
    float* pcat = (float*)(smu + 11520);
    float* pm   = (float*)(smu + 19968);
    float* ps   = (float*)(smu + 20096);
    const __half* QH = (const __half*)QF;
    const __half* RH = (const __half*)RF;
    const __half* KH = (const __half*)KF;
    const __half* PH = (const __half*)PF;

    const int tid = threadIdx.x;
    const int lane = tid & 31, warp = tid >> 5;
    const int g = lane >> 2, tig = lane & 3;
    const int qm = (warp & 3) << 4;
    const int wn = (warp >> 2) << 5;
    const int wcol = warp >> 2;

    const int lr = tid >> 4;             // 0..15
    const int lc4 = (tid & 15) << 2;     // half col (0..60)
    const int lc2 = (tid & 15) << 1;     // half2 col

    // per-thread LN constants (column-dependent only)
    const float4 qga = *(const float4*)&qgam[h * HDd + lc4];
    const float4 qbe = *(const float4*)&qbet[h * HDd + lc4];
    const float4 kga = *(const float4*)&kgam[h * HDd + lc4];
    const float4 kbe = *(const float4*)&kbet[h * HDd + lc4];

    // ---- Q block with LN applied ----
    {
        const float* qbase = qkv + (size_t)(b * Td + q0) * QKVN + h * HDd;
        #pragma unroll
        for (int i = 0; i < 4; i++) {
            int r = lr + (i << 4);
            float2 st = qstat[b * Td + q0 + r];
            float4 v = *(const float4*)&qbase[(size_t)r * QKVN + lc4];
            v.x = (v.x - st.x) * st.y * qga.x + qbe.x;
            v.y = (v.y - st.x) * st.y * qga.y + qbe.y;
            v.z = (v.z - st.x) * st.y * qga.z + qbe.z;
            v.w = (v.w - st.x) * st.y * qga.w + qbe.w;
            *(uint2*)&QF[r * TP2 + lc2] = pack4(v);
        }
    }

    float o[4][4] = {};
    float m0_ = -1e30f, m1_ = -1e30f, l0_ = 0.f, l1_ = 0.f;
    const float scale = 0.125f;
    const int r0 = qm + g, r1 = qm + g + 8;

    for (int kt = 0; kt < ntiles; kt++) {
        const int D = q0 - (kt << 6);
        const bool haveLo = (D != 0);

        // ---- K tile (LN applied) + rel band ----
        {
            const float* kbase = qkv + (size_t)(b * Td + (kt << 6)) * QKVN + Cd + h * HDd;
            #pragma unroll
            for (int i = 0; i < 4; i++) {
                int r = lr + (i << 4);
                float2 st = kstat[b * Td + (kt << 6) + r];
                float4 v = *(const float4*)&kbase[(size_t)r * QKVN + lc4];
                v.x = (v.x - st.x) * st.y * kga.x + kbe.x;
                v.y = (v.y - st.x) * st.y * kga.y + kbe.y;
                v.z = (v.z - st.x) * st.y * kga.z + kbe.z;
                v.w = (v.w - st.x) * st.y * kga.w + kbe.w;
                *(uint2*)&KF[r * TP2 + lc2] = pack4(v);
            }
            #pragma unroll
            for (int i = 0; i < 8; i++) {
                int rr = lr + (i << 4);              // 0..127
                int delta = D - 64 + rr;
                if (delta >= 0) {
                    float4 v = *(const float4*)&rel_emb[(size_t)delta * Cd + h * HDd + lc4];
                    *(uint2*)&RF[(rr >> 6) * 2304 + (rr & 63) * TP2 + lc2] = pack4(v);
                }
            }
        }
        __syncthreads();   // (a)

        // ---- MMA: S = Q K^T ; P = Q rel^T ----
        float cS[4][4] = {};
        float cP1[4][4] = {};
        float cP0[4][4] = {};
        #pragma unroll
        for (int ks = 0; ks < 4; ks++) {
            const int ko = ks << 4;
            unsigned aq[4];
            ldA(aq, QH, TPH, qm, ko, lane);
            unsigned bk[2][4], bh[2][4], bl[2][4];
            ldB2(bk[0], KH, TPH, wn, ko, lane);
            ldB2(bk[1], KH, TPH, wn + 16, ko, lane);
            ldB2(bh[0], RH + 4608, TPH, wn, ko, lane);
            ldB2(bh[1], RH + 4608, TPH, wn + 16, ko, lane);
            if (haveLo) {
                ldB2(bl[0], RH, TPH, wn, ko, lane);
                ldB2(bl[1], RH, TPH, wn + 16, ko, lane);
            }
            #pragma unroll
            for (int j = 0; j < 4; j++) {
                int p = j >> 1, q = (j & 1) << 1;
                mma_f16(cS[j], aq[0], aq[1], aq[2], aq[3], bk[p][q], bk[p][q + 1]);
                mma_f16(cP1[j], aq[0], aq[1], aq[2], aq[3], bh[p][q], bh[p][q + 1]);
                if (haveLo)
                    mma_f16(cP0[j], aq[0], aq[1], aq[2], aq[3], bl[p][q], bl[p][q + 1]);
            }
        }
        #pragma unroll
        for (int j = 0; j < 4; j++) {
            int col = wn + (j << 3) + (tig << 1);
            if (haveLo) {
                *(float2*)&pcat[r0 * PCP + col] = make_float2(cP0[j][0], cP0[j][1]);
                *(float2*)&pcat[r1 * PCP + col] = make_float2(cP0[j][2], cP0[j][3]);
            }
            *(float2*)&pcat[r0 * PCP + 64 + col] = make_float2(cP1[j][0], cP1[j][1]);
            *(float2*)&pcat[r1 * PCP + 64 + col] = make_float2(cP1[j][2], cP1[j][3]);
        }
        __syncthreads();   // (b)

        // ---- V tile transposed [d][key] into RF slot 0 ----
        {
            __half* VH = (__half*)RF;
            const float* vbase = qkv + (size_t)(b * Td + (kt << 6)) * QKVN + 2 * Cd + h * HDd;
            #pragma unroll
            for (int i = 0; i < 4; i++) {
                int key = lr + (i << 4);
                float4 v = *(const float4*)&vbase[(size_t)key * QKVN + lc4];
                VH[(lc4 + 0) * TPH + key] = __float2half_rn(v.x);
                VH[(lc4 + 1) * TPH + key] = __float2half_rn(v.y);
                VH[(lc4 + 2) * TPH + key] = __float2half_rn(v.z);
                VH[(lc4 + 3) * TPH + key] = __float2half_rn(v.w);
            }
        }

        // ---- scores in registers: mask + bias + scale ----
        float s_[4][4];
        #pragma unroll
        for (int j = 0; j < 4; j++) {
            #pragma unroll
            for (int u = 0; u < 2; u++) {
                int c = wn + (j << 3) + (tig << 1) + u;
                s_[j][u] = (r0 - c + D >= 0)
                    ? (cS[j][u] + pcat[r0 * PCP + 64 + r0 - c]) * scale : -1e30f;
                s_[j][2 + u] = (r1 - c + D >= 0)
                    ? (cS[j][2 + u] + pcat[r1 * PCP + 64 + r1 - c]) * scale : -1e30f;
            }
        }
        float mx0 = -1e30f, mx1 = -1e30f;
        #pragma unroll
        for (int j = 0; j < 4; j++) {
            mx0 = fmaxf(mx0, fmaxf(s_[j][0], s_[j][1]));
            mx1 = fmaxf(mx1, fmaxf(s_[j][2], s_[j][3]));
        }
        #pragma unroll
        for (int oo = 1; oo <= 2; oo <<= 1) {
            mx0 = fmaxf(mx0, __shfl_xor_sync(0xffffffffu, mx0, oo));
            mx1 = fmaxf(mx1, __shfl_xor_sync(0xffffffffu, mx1, oo));
        }
        if (tig == 0) { pm[wcol * 64 + r0] = mx0; pm[wcol * 64 + r1] = mx1; }
        __syncthreads();   // (c)

        float mn0 = fmaxf(m0_, fmaxf(mx0, pm[(1 - wcol) * 64 + r0]));
        float mn1 = fmaxf(m1_, fmaxf(mx1, pm[(1 - wcol) * 64 + r1]));
        float al0 = __expf(m0_ - mn0), al1 = __expf(m1_ - mn1);
        m0_ = mn0; m1_ = mn1;

        float sum0 = 0.f, sum1 = 0.f;
        #pragma unroll
        for (int j = 0; j < 4; j++) {
            float p00 = __expf(s_[j][0] - mn0);
            float p01 = __expf(s_[j][1] - mn0);
            float p10 = __expf(s_[j][2] - mn1);
            float p11 = __expf(s_[j][3] - mn1);
            sum0 += p00 + p01; sum1 += p10 + p11;
            int cw = (wn >> 1) + (j << 2) + tig;
            PF[r0 * TP2 + cw] = f2h2(p00, p01);
            PF[r1 * TP2 + cw] = f2h2(p10, p11);
        }
        #pragma unroll
        for (int oo = 1; oo <= 2; oo <<= 1) {
            sum0 += __shfl_xor_sync(0xffffffffu, sum0, oo);
            sum1 += __shfl_xor_sync(0xffffffffu, sum1, oo);
        }
        if (tig == 0) { ps[wcol * 64 + r0] = sum0; ps[wcol * 64 + r1] = sum1; }
        __syncthreads();   // (d)

        l0_ = l0_ * al0 + sum0 + ps[(1 - wcol) * 64 + r0];
        l1_ = l1_ * al1 + sum1 + ps[(1 - wcol) * 64 + r1];

        #pragma unroll
        for (int j = 0; j < 4; j++) {
            o[j][0] *= al0; o[j][1] *= al0;
            o[j][2] *= al1; o[j][3] *= al1;
        }
        // ---- O += P @ V ----
        #pragma unroll
        for (int ks = 0; ks < 4; ks++) {
            const int ko = ks << 4;
            unsigned ap[4];
            ldA(ap, PH, TPH, qm, ko, lane);
            unsigned bv[2][4];
            ldB2(bv[0], RH, TPH, wn, ko, lane);
            ldB2(bv[1], RH, TPH, wn + 16, ko, lane);
            #pragma unroll
            for (int j = 0; j < 4; j++) {
                int p = j >> 1, q = (j & 1) << 1;
                mma_f16(o[j], ap[0], ap[1], ap[2], ap[3], bv[p][q], bv[p][q + 1]);
            }
        }
        __syncthreads();   // (e)
    }

    // ---- finalize ----
    {
        float inv0 = 1.0f / l0_, inv1 = 1.0f / l1_;
        int row = b * Td + q0 + r0;
        #pragma unroll
        for (int j = 0; j < 4; j++) {
            int col = h * HDd + wn + (j << 3) + (tig << 1);
            *(float2*)&yout[(size_t)row * Cd + col] =
                make_float2(o[j][0] * inv0, o[j][1] * inv0);
            *(float2*)&yout[(size_t)(row + 8) * Cd + col] =
                make_float2(o[j][2] * inv1, o[j][3] * inv1);
        }
    }
}

// ---------------------------------------------------------------------------
extern "C" void kernel_launch(void* const* d_in, const int* in_sizes, int n_in,
                              void* d_out, int out_size)
{
    const float* x      = (const float*)d_in[0];
    const float* w_attn = (const float*)d_in[1];
    const float* b_attn = (const float*)d_in[2];
    const float* w_proj = (const float*)d_in[3];
    const float* b_proj = (const float*)d_in[4];
    const float* qg     = (const float*)d_in[5];
    const float* qbeta  = (const float*)d_in[6];
    const float* kg     = (const float*)d_in[7];
    const float* kbeta  = (const float*)d_in[8];
    const float* rel    = (const float*)d_in[9];
    float* out = (float*)d_out;

    float *qkv_p, *y_p;
    float2 *qs_p, *ks_p;
    cudaGetSymbolAddress((void**)&qkv_p, g_qkv);
    cudaGetSymbolAddress((void**)&y_p, g_y);
    cudaGetSymbolAddress((void**)&qs_p, g_qstat);
    cudaGetSymbolAddress((void**)&ks_p, g_kstat);

    cudaFuncSetAttribute(attn_kernel,
                         cudaFuncAttributeMaxDynamicSharedMemorySize, ATTN_SMEM);

    // 1) QKV projection
    {
        dim3 grid(QKVN / 64, Md / 128);
        sgemm_bias_kernel<128><<<grid, 256>>>(x, w_attn, b_attn, qkv_p, Cd, QKVN);
    }
    // 2) per-row LN stats for q,k
    ln_stats_kernel<<<Md * 2 * 32 / 256, 256>>>(qkv_p, qs_p, ks_p);
    // 3) Flash attention (LN fused into operand fill)
    attn_kernel<<<Bd * NHd * (Td / 64), 256, ATTN_SMEM>>>(
        qkv_p, rel, qs_p, ks_p, qg, qbeta, kg, kbeta, y_p);
    // 4) Output projection
    {
        dim3 grid(Cd / 64, Md / 64);
        sgemm_bias_kernel<64><<<grid, 256>>>(y_p, w_proj, b_proj, out, Cd, Cd);
    }
}

// round 17
// speedup vs baseline: 1.0825x; 1.0825x over previous
#include <cuda_runtime.h>
#include <cuda_fp16.h>

#define Bd 8
#define Td 512
#define Cd 512
#define NHd 8
#define HDd 64
#define Md (Bd * Td)            // 4096
#define QKVN (3 * Cd)           // 1536

__device__ float g_qkv[Md * QKVN];
__device__ float g_y[Md * Cd];
__device__ float2 g_qstat[Md];
__device__ float2 g_kstat[Md];

// pack two floats into half2 bits (lo, hi)
__device__ __forceinline__ unsigned f2h2(float lo, float hi) {
    unsigned u;
    asm("cvt.rn.f16x2.f32 %0, %1, %2;" : "=r"(u) : "f"(hi), "f"(lo));
    return u;
}
__device__ __forceinline__ uint2 pack4(float4 v) {
    return make_uint2(f2h2(v.x, v.y), f2h2(v.z, v.w));
}
__device__ __forceinline__ void mma_f16(float c[4],
    unsigned a0, unsigned a1, unsigned a2, unsigned a3,
    unsigned b0, unsigned b1)
{
    asm volatile(
        "mma.sync.aligned.m16n8k16.row.col.f32.f16.f16.f32 "
        "{%0,%1,%2,%3}, {%4,%5,%6,%7}, {%8,%9}, {%0,%1,%2,%3};"
        : "+f"(c[0]), "+f"(c[1]), "+f"(c[2]), "+f"(c[3])
        : "r"(a0), "r"(a1), "r"(a2), "r"(a3), "r"(b0), "r"(b1));
}

__device__ __forceinline__ unsigned smaddr(const void* p) {
    return (unsigned)__cvta_generic_to_shared(p);
}
__device__ __forceinline__ void ldsm_x4(unsigned& r0, unsigned& r1,
                                        unsigned& r2, unsigned& r3, unsigned addr) {
    asm volatile("ldmatrix.sync.aligned.m8n8.x4.shared.b16 {%0,%1,%2,%3}, [%4];"
        : "=r"(r0), "=r"(r1), "=r"(r2), "=r"(r3) : "r"(addr));
}
// A-fragment m16xk16 at rows rb..rb+15, halfs ko..ko+15
__device__ __forceinline__ void ldA(unsigned a[4], const __half* base, int pitch,
                                    int rb, int ko, int lane) {
    int row = rb + (lane & 15);
    int kk = ko + ((lane >> 4) << 3);
    unsigned addr = smaddr(base + row * pitch + kk);
    ldsm_x4(a[0], a[1], a[2], a[3], addr);
}
// B-fragments for TWO n8 subtiles (rows nb..nb+15), halfs ko..ko+15
__device__ __forceinline__ void ldB2(unsigned b[4], const __half* base, int pitch,
                                     int nb, int ko, int lane) {
    int row = nb + (lane & 7) + ((lane >> 4) << 3);
    int kk = ko + (((lane >> 3) & 1) << 3);
    unsigned addr = smaddr(base + row * pitch + kk);
    ldsm_x4(b[0], b[1], b[2], b[3], addr);
}

// ---------------------------------------------------------------------------
// fp16 SGEMM, scalar-LDS operands, double-buffered smem (unchanged from R15).
// ---------------------------------------------------------------------------
#define GP2 20
template<int BM>
__global__ __launch_bounds__(256) void sgemm_bias_kernel(
    const float* __restrict__ A, const float* __restrict__ W,
    const float* __restrict__ bias, float* __restrict__ out,
    int Kdim, int Ndim)
{
    constexpr int MI = BM / 64;
    constexpr int AL = BM / 32;
    __shared__ unsigned As[2][BM * GP2];
    __shared__ unsigned Bs[2][64 * GP2];
    const int tid = threadIdx.x;
    const int lane = tid & 31, warp = tid >> 5;
    const int g = lane >> 2, tig = lane & 3;
    const int wm = (warp & 3) * (BM / 4);
    const int wn = (warp >> 2) << 5;
    const int m0 = blockIdx.y * BM, n0 = blockIdx.x << 6;

    const int lrow = tid >> 3;
    const int lk4 = (tid & 7) << 2;
    const int lk2 = lk4 >> 1;

    float c[MI][4][4] = {};
    float4 avr[AL], bvr[2];

    const int niter = Kdim >> 5;

    #pragma unroll
    for (int i = 0; i < AL; i++)
        avr[i] = *(const float4*)&A[(size_t)(m0 + lrow + (i << 5)) * Kdim + lk4];
    #pragma unroll
    for (int i = 0; i < 2; i++)
        bvr[i] = *(const float4*)&W[(size_t)(n0 + lrow + (i << 5)) * Kdim + lk4];
    #pragma unroll
    for (int i = 0; i < AL; i++)
        *(uint2*)&As[0][(lrow + (i << 5)) * GP2 + lk2] = pack4(avr[i]);
    #pragma unroll
    for (int i = 0; i < 2; i++)
        *(uint2*)&Bs[0][(lrow + (i << 5)) * GP2 + lk2] = pack4(bvr[i]);
    if (niter > 1) {
        #pragma unroll
        for (int i = 0; i < AL; i++)
            avr[i] = *(const float4*)&A[(size_t)(m0 + lrow + (i << 5)) * Kdim + 32 + lk4];
        #pragma unroll
        for (int i = 0; i < 2; i++)
            bvr[i] = *(const float4*)&W[(size_t)(n0 + lrow + (i << 5)) * Kdim + 32 + lk4];
    }
    __syncthreads();

    for (int it = 0; it < niter; it++) {
        const int p = it & 1;
        if (it + 1 < niter) {
            #pragma unroll
            for (int i = 0; i < AL; i++)
                *(uint2*)&As[p ^ 1][(lrow + (i << 5)) * GP2 + lk2] = pack4(avr[i]);
            #pragma unroll
            for (int i = 0; i < 2; i++)
                *(uint2*)&Bs[p ^ 1][(lrow + (i << 5)) * GP2 + lk2] = pack4(bvr[i]);
        }
        if (it + 2 < niter) {
            const int kn = (it + 2) << 5;
            #pragma unroll
            for (int i = 0; i < AL; i++)
                avr[i] = *(const float4*)&A[(size_t)(m0 + lrow + (i << 5)) * Kdim + kn + lk4];
            #pragma unroll
            for (int i = 0; i < 2; i++)
                bvr[i] = *(const float4*)&W[(size_t)(n0 + lrow + (i << 5)) * Kdim + kn + lk4];
        }

        #pragma unroll
        for (int ks = 0; ks < 2; ks++) {
            const int ko = ks << 3;
            unsigned a[MI][4];
            #pragma unroll
            for (int i = 0; i < MI; i++) {
                int mb = wm + (i << 4);
                a[i][0] = As[p][(mb + g) * GP2 + ko + tig];
                a[i][1] = As[p][(mb + g + 8) * GP2 + ko + tig];
                a[i][2] = As[p][(mb + g) * GP2 + ko + 4 + tig];
                a[i][3] = As[p][(mb + g + 8) * GP2 + ko + 4 + tig];
            }
            #pragma unroll
            for (int j = 0; j < 4; j++) {
                int nb = wn + (j << 3) + g;
                unsigned b0 = Bs[p][nb * GP2 + ko + tig];
                unsigned b1 = Bs[p][nb * GP2 + ko + 4 + tig];
                #pragma unroll
                for (int i = 0; i < MI; i++)
                    mma_f16(c[i][j], a[i][0], a[i][1], a[i][2], a[i][3], b0, b1);
            }
        }
        __syncthreads();
    }

    #pragma unroll
    for (int i = 0; i < MI; i++) {
        #pragma unroll
        for (int j = 0; j < 4; j++) {
            int row = m0 + wm + (i << 4) + g;
            int col = n0 + wn + (j << 3) + (tig << 1);
            float b0 = bias[col], b1 = bias[col + 1];
            *(float2*)&out[(size_t)row * Ndim + col] =
                make_float2(c[i][j][0] + b0, c[i][j][1] + b1);
            *(float2*)&out[(size_t)(row + 8) * Ndim + col] =
                make_float2(c[i][j][2] + b0, c[i][j][3] + b1);
        }
    }
}

// ---------------------------------------------------------------------------
// Per-row LN stats (mu, rstd) for q and k segments. One warp per row-segment.
// ---------------------------------------------------------------------------
__global__ __launch_bounds__(256) void ln_stats_kernel(
    const float* __restrict__ qkv,
    float2* __restrict__ qstat, float2* __restrict__ kstat)
{
    const int gw = (blockIdx.x * 256 + threadIdx.x) >> 5;
    const int lane = threadIdx.x & 31;
    const int row = gw >> 1, seg = gw & 1;
    const float* p = qkv + (size_t)row * QKVN + seg * Cd;
    float s = 0.f, ss = 0.f;
    #pragma unroll
    for (int i = 0; i < 4; i++) {
        float4 v = *(const float4*)&p[(lane << 2) + (i << 7)];
        s  += v.x + v.y + v.z + v.w;
        ss += v.x * v.x + v.y * v.y + v.z * v.z + v.w * v.w;
    }
    #pragma unroll
    for (int o = 16; o; o >>= 1) {
        s  += __shfl_xor_sync(0xffffffffu, s, o);
        ss += __shfl_xor_sync(0xffffffffu, ss, o);
    }
    if (lane == 0) {
        float mu = s * (1.0f / 512.0f);
        float var = ss * (1.0f / 512.0f) - mu * mu;
        float2 st = make_float2(mu, rsqrtf(var + 1e-5f));
        if (seg) kstat[row] = st; else qstat[row] = st;
    }
}

// ---------------------------------------------------------------------------
// Flash attention with rolling rel-tile reuse (pcat indexed by delta & 127).
// Each 64-delta rel tile's P is computed exactly once per CTA.
// smem words: QF 2304 | RF0 2304 | RF1 2304 | VF 2304 | KF 2304 | PF 2304 |
//             pcat 8448 | pm 128 | ps 128  = 22528 words = 90112 bytes
// ---------------------------------------------------------------------------
#define TP2 36
#define TPH 72
#define PCP 132
#define ATTN_SMEM (22528 * 4)

__global__ __launch_bounds__(256, 2) void attn_kernel(
    const float* __restrict__ qkv,
    const float* __restrict__ rel_emb,
    const float2* __restrict__ qstat, const float2* __restrict__ kstat,
    const float* __restrict__ qgam, const float* __restrict__ qbet,
    const float* __restrict__ kgam, const float* __restrict__ kbet,
    float* __restrict__ yout)
{
    const int blk = blockIdx.x;
    const int qb = 7 - (blk & 7);        // heavy blocks first
    const int h  = (blk >> 3) & 7;
    const int b  = blk >> 6;
    const int q0 = qb << 6;
    const int ntiles = qb + 1;

    extern __shared__ unsigned smu[];
    unsigned* QF  = smu;                 // Q [row][k]
    unsigned* RF0 = smu + 2304;          // new (lo) rel tile
    unsigned* RF1 = smu + 4608;          // hi rel tile (kt==0 only)
    unsigned* VF  = smu + 6912;          // V transposed [d][key]
    unsigned* KF  = smu + 9216;          // K [key][d]
    unsigned* PF  = smu + 11520;         // probabilities [row][key]
    float* pcat = (float*)(smu + 13824); // P band, col = delta & 127
    float* pm   = (float*)(smu + 22272);
    float* ps   = (float*)(smu + 22400);
    const __half* QH  = (const __half*)QF;
    const __half* RH0 = (const __half*)RF0;
    const __half* RH1 = (const __half*)RF1;
    const __half* VH  = (const __half*)VF;
    const __half* KH  = (const __half*)KF;
    const __half* PH  = (const __half*)PF;

    const int tid = threadIdx.x;
    const int lane = tid & 31, warp = tid >> 5;
    const int g = lane >> 2, tig = lane & 3;
    const int qm = (warp & 3) << 4;
    const int wn = (warp >> 2) << 5;
    const int wcol = warp >> 2;

    const int lr = tid >> 4;             // 0..15
    const int lc4 = (tid & 15) << 2;     // half col (0..60)
    const int lc2 = (tid & 15) << 1;     // half2 col

    const float4 qga = *(const float4*)&qgam[h * HDd + lc4];
    const float4 qbe = *(const float4*)&qbet[h * HDd + lc4];
    const float4 kga = *(const float4*)&kgam[h * HDd + lc4];
    const float4 kbe = *(const float4*)&kbet[h * HDd + lc4];

    // ---- Q block with LN applied ----
    {
        const float* qbase = qkv + (size_t)(b * Td + q0) * QKVN + h * HDd;
        #pragma unroll
        for (int i = 0; i < 4; i++) {
            int r = lr + (i << 4);
            float2 st = qstat[b * Td + q0 + r];
            float4 v = *(const float4*)&qbase[(size_t)r * QKVN + lc4];
            v.x = (v.x - st.x) * st.y * qga.x + qbe.x;
            v.y = (v.y - st.x) * st.y * qga.y + qbe.y;
            v.z = (v.z - st.x) * st.y * qga.z + qbe.z;
            v.w = (v.w - st.x) * st.y * qga.w + qbe.w;
            *(uint2*)&QF[r * TP2 + lc2] = pack4(v);
        }
    }

    float o[4][4] = {};
    float m0_ = -1e30f, m1_ = -1e30f, l0_ = 0.f, l1_ = 0.f;
    const float scale = 0.125f;
    const int r0 = qm + g, r1 = qm + g + 8;

    for (int kt = 0; kt < ntiles; kt++) {
        const int D = q0 - (kt << 6);
        const int rt = qb - kt - 1;      // new rel tile this iteration

        // ---- fills: K (LN), V (transposed), rel tiles ----
        {
            const float* kbase = qkv + (size_t)(b * Td + (kt << 6)) * QKVN + Cd + h * HDd;
            #pragma unroll
            for (int i = 0; i < 4; i++) {
                int r = lr + (i << 4);
                float2 st = kstat[b * Td + (kt << 6) + r];
                float4 v = *(const float4*)&kbase[(size_t)r * QKVN + lc4];
                v.x = (v.x - st.x) * st.y * kga.x + kbe.x;
                v.y = (v.y - st.x) * st.y * kga.y + kbe.y;
                v.z = (v.z - st.x) * st.y * kga.z + kbe.z;
                v.w = (v.w - st.x) * st.y * kga.w + kbe.w;
                *(uint2*)&KF[r * TP2 + lc2] = pack4(v);
            }
            const float* vbase = qkv + (size_t)(b * Td + (kt << 6)) * QKVN + 2 * Cd + h * HDd;
            __half* VW = (__half*)VF;
            #pragma unroll
            for (int i = 0; i < 4; i++) {
                int key = lr + (i << 4);
                float4 v = *(const float4*)&vbase[(size_t)key * QKVN + lc4];
                VW[(lc4 + 0) * TPH + key] = __float2half_rn(v.x);
                VW[(lc4 + 1) * TPH + key] = __float2half_rn(v.y);
                VW[(lc4 + 2) * TPH + key] = __float2half_rn(v.z);
                VW[(lc4 + 3) * TPH + key] = __float2half_rn(v.w);
            }
            if (rt >= 0) {
                #pragma unroll
                for (int i = 0; i < 4; i++) {
                    int rr = lr + (i << 4);
                    float4 v = *(const float4*)&rel_emb[(size_t)((rt << 6) + rr) * Cd + h * HDd + lc4];
                    *(uint2*)&RF0[rr * TP2 + lc2] = pack4(v);
                }
            }
            if (kt == 0) {
                #pragma unroll
                for (int i = 0; i < 4; i++) {
                    int rr = lr + (i << 4);
                    float4 v = *(const float4*)&rel_emb[(size_t)((qb << 6) + rr) * Cd + h * HDd + lc4];
                    *(uint2*)&RF1[rr * TP2 + lc2] = pack4(v);
                }
            }
        }
        __syncthreads();   // (a)

        // ---- MMA: S = Q K^T ; P for new rel tile(s) ----
        float cS[4][4] = {};
        float cPn[4][4] = {};
        float cPh[4][4] = {};
        #pragma unroll
        for (int ks = 0; ks < 4; ks++) {
            const int ko = ks << 4;
            unsigned aq[4];
            ldA(aq, QH, TPH, qm, ko, lane);
            unsigned bk[2][4], bn[2][4], bh[2][4];
            ldB2(bk[0], KH, TPH, wn, ko, lane);
            ldB2(bk[1], KH, TPH, wn + 16, ko, lane);
            if (rt >= 0) {
                ldB2(bn[0], RH0, TPH, wn, ko, lane);
                ldB2(bn[1], RH0, TPH, wn + 16, ko, lane);
            }
            if (kt == 0) {
                ldB2(bh[0], RH1, TPH, wn, ko, lane);
                ldB2(bh[1], RH1, TPH, wn + 16, ko, lane);
            }
            #pragma unroll
            for (int j = 0; j < 4; j++) {
                int p = j >> 1, q = (j & 1) << 1;
                mma_f16(cS[j], aq[0], aq[1], aq[2], aq[3], bk[p][q], bk[p][q + 1]);
                if (rt >= 0)
                    mma_f16(cPn[j], aq[0], aq[1], aq[2], aq[3], bn[p][q], bn[p][q + 1]);
                if (kt == 0)
                    mma_f16(cPh[j], aq[0], aq[1], aq[2], aq[3], bh[p][q], bh[p][q + 1]);
            }
        }
        // write P into pcat at col = delta & 127
        if (rt >= 0) {
            const int basen = (rt & 1) << 6;
            #pragma unroll
            for (int j = 0; j < 4; j++) {
                int col = basen + wn + (j << 3) + (tig << 1);
                *(float2*)&pcat[r0 * PCP + col] = make_float2(cPn[j][0], cPn[j][1]);
                *(float2*)&pcat[r1 * PCP + col] = make_float2(cPn[j][2], cPn[j][3]);
            }
        }
        if (kt == 0) {
            const int baseh = (qb & 1) << 6;
            #pragma unroll
            for (int j = 0; j < 4; j++) {
                int col = baseh + wn + (j << 3) + (tig << 1);
                *(float2*)&pcat[r0 * PCP + col] = make_float2(cPh[j][0], cPh[j][1]);
                *(float2*)&pcat[r1 * PCP + col] = make_float2(cPh[j][2], cPh[j][3]);
            }
        }
        __syncthreads();   // (b)

        // ---- scores in registers: mask + bias + scale ----
        float s_[4][4];
        #pragma unroll
        for (int j = 0; j < 4; j++) {
            #pragma unroll
            for (int u = 0; u < 2; u++) {
                int c = wn + (j << 3) + (tig << 1) + u;
                int d0 = r0 - c + D, d1 = r1 - c + D;
                s_[j][u] = (d0 >= 0)
                    ? (cS[j][u] + pcat[r0 * PCP + (d0 & 127)]) * scale : -1e30f;
                s_[j][2 + u] = (d1 >= 0)
                    ? (cS[j][2 + u] + pcat[r1 * PCP + (d1 & 127)]) * scale : -1e30f;
            }
        }
        float mx0 = -1e30f, mx1 = -1e30f;
        #pragma unroll
        for (int j = 0; j < 4; j++) {
            mx0 = fmaxf(mx0, fmaxf(s_[j][0], s_[j][1]));
            mx1 = fmaxf(mx1, fmaxf(s_[j][2], s_[j][3]));
        }
        #pragma unroll
        for (int oo = 1; oo <= 2; oo <<= 1) {
            mx0 = fmaxf(mx0, __shfl_xor_sync(0xffffffffu, mx0, oo));
            mx1 = fmaxf(mx1, __shfl_xor_sync(0xffffffffu, mx1, oo));
        }
        if (tig == 0) { pm[wcol * 64 + r0] = mx0; pm[wcol * 64 + r1] = mx1; }
        __syncthreads();   // (c)

        float mn0 = fmaxf(m0_, fmaxf(mx0, pm[(1 - wcol) * 64 + r0]));
        float mn1 = fmaxf(m1_, fmaxf(mx1, pm[(1 - wcol) * 64 + r1]));
        float al0 = __expf(m0_ - mn0), al1 = __expf(m1_ - mn1);
        m0_ = mn0; m1_ = mn1;

        float sum0 = 0.f, sum1 = 0.f;
        #pragma unroll
        for (int j = 0; j < 4; j++) {
            float p00 = __expf(s_[j][0] - mn0);
            float p01 = __expf(s_[j][1] - mn0);
            float p10 = __expf(s_[j][2] - mn1);
            float p11 = __expf(s_[j][3] - mn1);
            sum0 += p00 + p01; sum1 += p10 + p11;
            int cw = (wn >> 1) + (j << 2) + tig;
            PF[r0 * TP2 + cw] = f2h2(p00, p01);
            PF[r1 * TP2 + cw] = f2h2(p10, p11);
        }
        #pragma unroll
        for (int oo = 1; oo <= 2; oo <<= 1) {
            sum0 += __shfl_xor_sync(0xffffffffu, sum0, oo);
            sum1 += __shfl_xor_sync(0xffffffffu, sum1, oo);
        }
        if (tig == 0) { ps[wcol * 64 + r0] = sum0; ps[wcol * 64 + r1] = sum1; }
        __syncthreads();   // (d)

        l0_ = l0_ * al0 + sum0 + ps[(1 - wcol) * 64 + r0];
        l1_ = l1_ * al1 + sum1 + ps[(1 - wcol) * 64 + r1];

        #pragma unroll
        for (int j = 0; j < 4; j++) {
            o[j][0] *= al0; o[j][1] *= al0;
            o[j][2] *= al1; o[j][3] *= al1;
        }
        // ---- O += P @ V ----
        #pragma unroll
        for (int ks = 0; ks < 4; ks++) {
            const int ko = ks << 4;
            unsigned ap[4];
            ldA(ap, PH, TPH, qm, ko, lane);
            unsigned bv[2][4];
            ldB2(bv[0], VH, TPH, wn, ko, lane);
            ldB2(bv[1], VH, TPH, wn + 16, ko, lane);
            #pragma unroll
            for (int j = 0; j < 4; j++) {
                int p = j >> 1, q = (j & 1) << 1;
                mma_f16(o[j], ap[0], ap[1], ap[2], ap[3], bv[p][q], bv[p][q + 1]);
            }
        }
        __syncthreads();   // (e)
    }

    // ---- finalize ----
    {
        float inv0 = 1.0f / l0_, inv1 = 1.0f / l1_;
        int row = b * Td + q0 + r0;
        #pragma unroll
        for (int j = 0; j < 4; j++) {
            int col = h * HDd + wn + (j << 3) + (tig << 1);
            *(float2*)&yout[(size_t)row * Cd + col] =
                make_float2(o[j][0] * inv0, o[j][1] * inv0);
            *(float2*)&yout[(size_t)(row + 8) * Cd + col] =
                make_float2(o[j][2] * inv1, o[j][3] * inv1);
        }
    }
}

// ---------------------------------------------------------------------------
extern "C" void kernel_launch(void* const* d_in, const int* in_sizes, int n_in,
                              void* d_out, int out_size)
{
    const float* x      = (const float*)d_in[0];
    const float* w_attn = (const float*)d_in[1];
    const float* b_attn = (const float*)d_in[2];
    const float* w_proj = (const float*)d_in[3];
    const float* b_proj = (const float*)d_in[4];
    const float* qg     = (const float*)d_in[5];
    const float* qbeta  = (const float*)d_in[6];
    const float* kg     = (const float*)d_in[7];
    const float* kbeta  = (const float*)d_in[8];
    const float* rel    = (const float*)d_in[9];
    float* out = (float*)d_out;

    float *qkv_p, *y_p;
    float2 *qs_p, *ks_p;
    cudaGetSymbolAddress((void**)&qkv_p, g_qkv);
    cudaGetSymbolAddress((void**)&y_p, g_y);
    cudaGetSymbolAddress((void**)&qs_p, g_qstat);
    cudaGetSymbolAddress((void**)&ks_p, g_kstat);

    cudaFuncSetAttribute(attn_kernel,
                         cudaFuncAttributeMaxDynamicSharedMemorySize, ATTN_SMEM);

    // 1) QKV projection
    {
        dim3 grid(QKVN / 64, Md / 128);
        sgemm_bias_kernel<128><<<grid, 256>>>(x, w_attn, b_attn, qkv_p, Cd, QKVN);
    }
    // 2) per-row LN stats for q,k
    ln_stats_kernel<<<Md * 2 * 32 / 256, 256>>>(qkv_p, qs_p, ks_p);
    // 3) Flash attention (LN fused, rolling rel reuse)
    attn_kernel<<<Bd * NHd * (Td / 64), 256, ATTN_SMEM>>>(
        qkv_p, rel, qs_p, ks_p, qg, qbeta, kg, kbeta, y_p);
    // 4) Output projection
    {
        dim3 grid(Cd / 64, Md / 64);
        sgemm_bias_kernel<64><<<grid, 256>>>(y_p, w_proj, b_proj, out, Cd, Cd);
    }
}